// round 2
// baseline (speedup 1.0000x reference)
#include <cuda_runtime.h>

// ---------------------------------------------------------------------------
// SelfAttentionLayer: x[1,4096,1024] -> out[1,4096,1024]
//   q = x@Wq^T+bq ; k = x@Wk^T+bk ; v = x@Wv^T+bv
//   per-head (16 heads, Dh=64) softmax(q k^T / 8) v
//   out = att@Wo^T+bo
// Round 1: fp32 baseline, vectorized loads (float4), BK=16 GEMM.
// ---------------------------------------------------------------------------

static const int S_LEN = 4096;
static const int EMB   = 1024;
static const int HDIM  = 64;    // head dim

// Scratch (allocation-free rule: __device__ globals)
__device__ float g_q[S_LEN * EMB];
__device__ float g_k[S_LEN * EMB];
__device__ float g_v[S_LEN * EMB];
__device__ float g_att[S_LEN * EMB];

// ---------------------------------------------------------------------------
// GEMM: C[M,N] = A[M,K] @ W[N,K]^T + bias[N]   (torch Linear semantics)
// BM=BN=128, BK=16, 256 threads, 8x8 microtile per thread, float4 loads.
// ---------------------------------------------------------------------------
#define GBM 128
#define GBN 128
#define GBK 16

__global__ __launch_bounds__(256)
void gemm_bias_kernel(const float* __restrict__ A, const float* __restrict__ W,
                      const float* __restrict__ bias, float* __restrict__ C,
                      int M, int N, int K)
{
    __shared__ float As[GBK][GBM + 4];
    __shared__ float Ws[GBK][GBN + 4];

    const int tid = threadIdx.x;
    const int tx = tid & 15;
    const int ty = tid >> 4;
    const int m0 = blockIdx.y * GBM;
    const int n0 = blockIdx.x * GBN;

    float acc[8][8];
#pragma unroll
    for (int i = 0; i < 8; i++)
#pragma unroll
        for (int j = 0; j < 8; j++) acc[i][j] = 0.0f;

    for (int k0 = 0; k0 < K; k0 += GBK) {
        // Load 128x16 tiles of A and W as float4 (2 per thread per matrix).
#pragma unroll
        for (int it = 0; it < 2; it++) {
            int idx = tid + it * 256;       // 0..511
            int r  = idx >> 2;              // 0..127
            int c4 = (idx & 3) * 4;         // 0,4,8,12
            float4 av = *(const float4*)&A[(size_t)(m0 + r) * K + k0 + c4];
            float4 wv = *(const float4*)&W[(size_t)(n0 + r) * K + k0 + c4];
            As[c4 + 0][r] = av.x; As[c4 + 1][r] = av.y;
            As[c4 + 2][r] = av.z; As[c4 + 3][r] = av.w;
            Ws[c4 + 0][r] = wv.x; Ws[c4 + 1][r] = wv.y;
            Ws[c4 + 2][r] = wv.z; Ws[c4 + 3][r] = wv.w;
        }
        __syncthreads();

#pragma unroll
        for (int kk = 0; kk < GBK; kk++) {
            float a[8], b[8];
#pragma unroll
            for (int i = 0; i < 8; i++) a[i] = As[kk][ty + 16 * i];
#pragma unroll
            for (int j = 0; j < 8; j++) b[j] = Ws[kk][tx + 16 * j];
#pragma unroll
            for (int i = 0; i < 8; i++)
#pragma unroll
                for (int j = 0; j < 8; j++)
                    acc[i][j] += a[i] * b[j];
        }
        __syncthreads();
    }

#pragma unroll
    for (int i = 0; i < 8; i++) {
        int m = m0 + ty + 16 * i;
#pragma unroll
        for (int j = 0; j < 8; j++) {
            int n = n0 + tx + 16 * j;
            C[(size_t)m * N + n] = acc[i][j] + bias[n];
        }
    }
}

// ---------------------------------------------------------------------------
// Flash attention (fp32). One block = (64 queries) x (1 head).
// Streams K/V in 64x64 tiles with online softmax. 256 threads, 4x4 microtiles.
// Dynamic smem: Qs/Ks/Vs/Ps, each 64x65 floats (pad avoids bank conflicts).
// ---------------------------------------------------------------------------
#define FP 65  // smem row pitch

__global__ __launch_bounds__(256)
void flash_kernel(const float* __restrict__ Q, const float* __restrict__ Km,
                  const float* __restrict__ Vm, float* __restrict__ O)
{
    extern __shared__ float sm[];
    float* Qs = sm;
    float* Ks = sm + 64 * FP;
    float* Vs = sm + 2 * 64 * FP;
    float* Ps = sm + 3 * 64 * FP;

    const int tid = threadIdx.x;
    const int tx = tid & 15;
    const int ty = tid >> 4;
    const int q0 = blockIdx.x * 64;
    const int hc = blockIdx.y * HDIM;     // head column offset
    const float scale = 0.125f;           // 1/sqrt(64)

    // Load Q tile [64 x 64] via float4 (consumed after first in-loop barrier)
#pragma unroll
    for (int it = 0; it < 4; it++) {
        int idx = tid + it * 256;         // 0..1023
        int r  = idx >> 4;                // 0..63
        int c4 = (idx & 15) * 4;          // 0..60
        float4 qv = *(const float4*)&Q[(size_t)(q0 + r) * EMB + hc + c4];
        Qs[r * FP + c4 + 0] = qv.x; Qs[r * FP + c4 + 1] = qv.y;
        Qs[r * FP + c4 + 2] = qv.z; Qs[r * FP + c4 + 3] = qv.w;
    }

    float m_i[4], l_i[4], acc[4][4];
#pragma unroll
    for (int i = 0; i < 4; i++) {
        m_i[i] = -1e30f;
        l_i[i] = 0.0f;
#pragma unroll
        for (int j = 0; j < 4; j++) acc[i][j] = 0.0f;
    }

    for (int t0 = 0; t0 < S_LEN; t0 += 64) {
        __syncthreads();   // previous PV done (and Q load visible on iter 0)
#pragma unroll
        for (int it = 0; it < 4; it++) {
            int idx = tid + it * 256;
            int r  = idx >> 4;
            int c4 = (idx & 15) * 4;
            float4 kv = *(const float4*)&Km[(size_t)(t0 + r) * EMB + hc + c4];
            float4 vv = *(const float4*)&Vm[(size_t)(t0 + r) * EMB + hc + c4];
            Ks[r * FP + c4 + 0] = kv.x; Ks[r * FP + c4 + 1] = kv.y;
            Ks[r * FP + c4 + 2] = kv.z; Ks[r * FP + c4 + 3] = kv.w;
            Vs[r * FP + c4 + 0] = vv.x; Vs[r * FP + c4 + 1] = vv.y;
            Vs[r * FP + c4 + 2] = vv.z; Vs[r * FP + c4 + 3] = vv.w;
        }
        __syncthreads();

        // S = Q K^T  (64x64x64)
        float s[4][4];
#pragma unroll
        for (int i = 0; i < 4; i++)
#pragma unroll
            for (int j = 0; j < 4; j++) s[i][j] = 0.0f;

#pragma unroll 16
        for (int kk = 0; kk < 64; kk++) {
            float a[4], b[4];
#pragma unroll
            for (int i = 0; i < 4; i++) a[i] = Qs[(ty + 16 * i) * FP + kk];
#pragma unroll
            for (int j = 0; j < 4; j++) b[j] = Ks[(tx + 16 * j) * FP + kk];
#pragma unroll
            for (int i = 0; i < 4; i++)
#pragma unroll
                for (int j = 0; j < 4; j++)
                    s[i][j] += a[i] * b[j];
        }

        // Online softmax per q-row. Row owned by the 16 lanes sharing ty
        // (they are consecutive lanes -> shfl width 16 works).
#pragma unroll
        for (int i = 0; i < 4; i++) {
            float rm = -1e30f;
#pragma unroll
            for (int j = 0; j < 4; j++) {
                s[i][j] *= scale;
                rm = fmaxf(rm, s[i][j]);
            }
#pragma unroll
            for (int off = 8; off >= 1; off >>= 1)
                rm = fmaxf(rm, __shfl_xor_sync(0xffffffffu, rm, off, 16));

            float mnew  = fmaxf(m_i[i], rm);
            float alpha = __expf(m_i[i] - mnew);
            float rs = 0.0f;
#pragma unroll
            for (int j = 0; j < 4; j++) {
                s[i][j] = __expf(s[i][j] - mnew);
                rs += s[i][j];
            }
#pragma unroll
            for (int off = 8; off >= 1; off >>= 1)
                rs += __shfl_xor_sync(0xffffffffu, rs, off, 16);

            l_i[i] = l_i[i] * alpha + rs;
            m_i[i] = mnew;
#pragma unroll
            for (int j = 0; j < 4; j++) acc[i][j] *= alpha;
#pragma unroll
            for (int j = 0; j < 4; j++)
                Ps[(ty + 16 * i) * FP + tx + 16 * j] = s[i][j];
        }
        __syncthreads();

        // O += P V  (64x64x64)
#pragma unroll 16
        for (int kk = 0; kk < 64; kk++) {
            float p[4], v[4];
#pragma unroll
            for (int i = 0; i < 4; i++) p[i] = Ps[(ty + 16 * i) * FP + kk];
#pragma unroll
            for (int j = 0; j < 4; j++) v[j] = Vs[kk * FP + tx + 16 * j];
#pragma unroll
            for (int i = 0; i < 4; i++)
#pragma unroll
                for (int j = 0; j < 4; j++)
                    acc[i][j] += p[i] * v[j];
        }
    }

    // Normalize and write
#pragma unroll
    for (int i = 0; i < 4; i++) {
        float inv = 1.0f / l_i[i];
        int r = q0 + ty + 16 * i;
#pragma unroll
        for (int j = 0; j < 4; j++)
            O[(size_t)r * EMB + hc + tx + 16 * j] = acc[i][j] * inv;
    }
}

// ---------------------------------------------------------------------------
// Launch
// ---------------------------------------------------------------------------
extern "C" void kernel_launch(void* const* d_in, const int* in_sizes, int n_in,
                              void* d_out, int out_size)
{
    const float* x  = (const float*)d_in[0];
    const float* Wq = (const float*)d_in[1];
    const float* bq = (const float*)d_in[2];
    const float* Wk = (const float*)d_in[3];
    const float* bk = (const float*)d_in[4];
    const float* Wv = (const float*)d_in[5];
    const float* bv = (const float*)d_in[6];
    const float* Wo = (const float*)d_in[7];
    const float* bo = (const float*)d_in[8];
    float* out = (float*)d_out;

    float *q, *k, *v, *att;
    cudaGetSymbolAddress((void**)&q,   g_q);
    cudaGetSymbolAddress((void**)&k,   g_k);
    cudaGetSymbolAddress((void**)&v,   g_v);
    cudaGetSymbolAddress((void**)&att, g_att);

    const int FLASH_SMEM = 4 * 64 * FP * (int)sizeof(float);  // 66560 B
    cudaFuncSetAttribute(flash_kernel,
                         cudaFuncAttributeMaxDynamicSharedMemorySize, FLASH_SMEM);

    dim3 ggrid(EMB / GBN, S_LEN / GBM);   // (8, 32)
    gemm_bias_kernel<<<ggrid, 256>>>(x, Wq, bq, q, S_LEN, EMB, EMB);
    gemm_bias_kernel<<<ggrid, 256>>>(x, Wk, bk, k, S_LEN, EMB, EMB);
    gemm_bias_kernel<<<ggrid, 256>>>(x, Wv, bv, v, S_LEN, EMB, EMB);

    dim3 fgrid(S_LEN / 64, 16);           // (64 q-blocks, 16 heads)
    flash_kernel<<<fgrid, 256, FLASH_SMEM>>>(q, k, v, att);

    gemm_bias_kernel<<<ggrid, 256>>>(att, Wo, bo, out, S_LEN, EMB, EMB);
}

// round 5
// speedup vs baseline: 3.1309x; 3.1309x over previous
#include <cuda_runtime.h>
#include <cuda_bf16.h>
#include <cstdint>

// ---------------------------------------------------------------------------
// SelfAttentionLayer: x[1,4096,1024] -> out[1,4096,1024]
// Round 5 (= Round 4 resubmit; infra failure, kernel never ran):
// ALL matmuls on tensor cores via mma.sync.m16n8k16.bf16 (sm_100-safe;
// tcgen05 unavailable: harness compiles PTX at compute_100 base).
// Split-bf16 (hi+lo, 3 products) everywhere for fp32-grade accuracy.
// ---------------------------------------------------------------------------

static const int S_LEN = 4096;
static const int EMB   = 1024;
#define PADW 72   // padded row width (bf16 elems) for all smem tiles

// Scratch (__device__ globals; allocation-free rule)
__device__ __nv_bfloat16 g_xhi[S_LEN * EMB];
__device__ __nv_bfloat16 g_xlo[S_LEN * EMB];
__device__ __nv_bfloat16 g_whi[4][EMB * EMB];
__device__ __nv_bfloat16 g_wlo[4][EMB * EMB];
__device__ __nv_bfloat16 g_qhi[S_LEN * EMB];
__device__ __nv_bfloat16 g_qlo[S_LEN * EMB];
__device__ __nv_bfloat16 g_khi[S_LEN * EMB];
__device__ __nv_bfloat16 g_klo[S_LEN * EMB];
__device__ __nv_bfloat16 g_vhi[S_LEN * EMB];
__device__ __nv_bfloat16 g_vlo[S_LEN * EMB];
__device__ __nv_bfloat16 g_ahi[S_LEN * EMB];
__device__ __nv_bfloat16 g_alo[S_LEN * EMB];

// ---------------------------------------------------------------------------
// Helpers
// ---------------------------------------------------------------------------
__device__ __forceinline__ uint32_t smem_u32(const void* p) {
    uint32_t a;
    asm("{ .reg .u64 t; cvta.to.shared.u64 t, %1; cvt.u32.u64 %0, t; }"
        : "=r"(a) : "l"(p));
    return a;
}

// pack2(lo, hi): bf16x2 with low half = bf16(lo), high half = bf16(hi)
__device__ __forceinline__ uint32_t pack2(float lo, float hi) {
    uint32_t d;
    asm("cvt.rn.bf16x2.f32 %0, %1, %2;" : "=r"(d) : "f"(hi), "f"(lo));
    return d;
}
__device__ __forceinline__ float bf16r(float x) {
    return __bfloat162float(__float2bfloat16(x));
}

__device__ __forceinline__ void ldsm_x4(uint32_t* r, uint32_t a) {
    asm volatile("ldmatrix.sync.aligned.m8n8.x4.shared.b16 {%0,%1,%2,%3}, [%4];"
        : "=r"(r[0]), "=r"(r[1]), "=r"(r[2]), "=r"(r[3]) : "r"(a));
}
__device__ __forceinline__ void ldsm_x4_t(uint32_t* r, uint32_t a) {
    asm volatile("ldmatrix.sync.aligned.m8n8.x4.trans.shared.b16 {%0,%1,%2,%3}, [%4];"
        : "=r"(r[0]), "=r"(r[1]), "=r"(r[2]), "=r"(r[3]) : "r"(a));
}

// D += A*B, m16n8k16, row.col, bf16 in / fp32 accum
__device__ __forceinline__ void mma_bf16(float* c, const uint32_t* a,
                                         uint32_t b0, uint32_t b1) {
    asm volatile(
        "mma.sync.aligned.m16n8k16.row.col.f32.bf16.bf16.f32 "
        "{%0,%1,%2,%3}, {%4,%5,%6,%7}, {%8,%9}, {%0,%1,%2,%3};"
        : "+f"(c[0]), "+f"(c[1]), "+f"(c[2]), "+f"(c[3])
        : "r"(a[0]), "r"(a[1]), "r"(a[2]), "r"(a[3]), "r"(b0), "r"(b1));
}

// ---------------------------------------------------------------------------
// Split fp32 -> bf16 hi/lo (float4 vectorized)
// ---------------------------------------------------------------------------
__global__ __launch_bounds__(256)
void split4_kernel(const float4* __restrict__ in, uint2* __restrict__ hi,
                   uint2* __restrict__ lo, int n4)
{
    int i = blockIdx.x * blockDim.x + threadIdx.x;
    if (i < n4) {
        float4 x = in[i];
        float h0 = bf16r(x.x), h1 = bf16r(x.y), h2 = bf16r(x.z), h3 = bf16r(x.w);
        uint2 H, L;
        H.x = pack2(x.x, x.y);           H.y = pack2(x.z, x.w);
        L.x = pack2(x.x - h0, x.y - h1); L.y = pack2(x.z - h2, x.w - h3);
        hi[i] = H;
        lo[i] = L;
    }
}

// ---------------------------------------------------------------------------
// GEMM: C[4096,1024] = A @ W^T + bias.  A,W split bf16 (hi/lo), 3 products.
// 128x128 CTA tile, 8 warps = 4(M) x 2(N), warp tile 32x64.
// Output: fp32 (Cf) OR split bf16 (Chi/Clo).
// ---------------------------------------------------------------------------
__global__ __launch_bounds__(256)
void gemm_tc(const __nv_bfloat16* __restrict__ Ahi, const __nv_bfloat16* __restrict__ Alo,
             const __nv_bfloat16* __restrict__ Whi, const __nv_bfloat16* __restrict__ Wlo,
             const float* __restrict__ bias, float* __restrict__ Cf,
             __nv_bfloat16* __restrict__ Chi, __nv_bfloat16* __restrict__ Clo)
{
    extern __shared__ __nv_bfloat16 sm[];
    __nv_bfloat16* sAh = sm;
    __nv_bfloat16* sAl = sAh + 128 * PADW;
    __nv_bfloat16* sWh = sAl + 128 * PADW;
    __nv_bfloat16* sWl = sWh + 128 * PADW;
    const uint32_t base = smem_u32(sm);
    const uint32_t bAh = base;
    const uint32_t bAl = base + 128 * PADW * 2;
    const uint32_t bWh = base + 2 * 128 * PADW * 2;
    const uint32_t bWl = base + 3 * 128 * PADW * 2;

    const int tid = threadIdx.x;
    const int lane = tid & 31;
    const int wid = tid >> 5;
    const int wm = wid & 3;            // 0..3 (M)
    const int wn = wid >> 2;           // 0..1 (N)
    const int m0 = blockIdx.y * 128;
    const int n0 = blockIdx.x * 128;

    float c[2][8][4];
#pragma unroll
    for (int mi = 0; mi < 2; mi++)
#pragma unroll
        for (int na = 0; na < 8; na++)
#pragma unroll
            for (int j = 0; j < 4; j++) c[mi][na][j] = 0.0f;

    for (int k0 = 0; k0 < EMB; k0 += 64) {
        __syncthreads();
#pragma unroll
        for (int it = 0; it < 4; it++) {
            int u = tid + it * 256;      // 0..1023
            int r = u >> 3;              // 0..127
            int c8 = (u & 7) * 8;        // 0..56
            size_t ga = (size_t)(m0 + r) * EMB + k0 + c8;
            size_t gw = (size_t)(n0 + r) * EMB + k0 + c8;
            *(uint4*)(sAh + r * PADW + c8) = *(const uint4*)(Ahi + ga);
            *(uint4*)(sAl + r * PADW + c8) = *(const uint4*)(Alo + ga);
            *(uint4*)(sWh + r * PADW + c8) = *(const uint4*)(Whi + gw);
            *(uint4*)(sWl + r * PADW + c8) = *(const uint4*)(Wlo + gw);
        }
        __syncthreads();

#pragma unroll
        for (int kc = 0; kc < 4; kc++) {
            uint32_t ah[2][4], al[2][4];
#pragma unroll
            for (int mi = 0; mi < 2; mi++) {
                uint32_t off = (uint32_t)(((wm * 32 + mi * 16 + (lane & 15)) * PADW
                                           + kc * 16 + ((lane >> 4) << 3)) * 2);
                ldsm_x4(ah[mi], bAh + off);
                ldsm_x4(al[mi], bAl + off);
            }
#pragma unroll
            for (int nj = 0; nj < 4; nj++) {
                uint32_t bh4[4], bl4[4];
                uint32_t off = (uint32_t)(((wn * 64 + nj * 16 + (lane & 15)) * PADW
                                           + kc * 16 + ((lane >> 4) << 3)) * 2);
                ldsm_x4(bh4, bWh + off);
                ldsm_x4(bl4, bWl + off);
#pragma unroll
                for (int mi = 0; mi < 2; mi++) {
                    // atom 2nj   : b = {R0, R2}
                    mma_bf16(c[mi][2 * nj], ah[mi], bh4[0], bh4[2]);
                    mma_bf16(c[mi][2 * nj], ah[mi], bl4[0], bl4[2]);
                    mma_bf16(c[mi][2 * nj], al[mi], bh4[0], bh4[2]);
                    // atom 2nj+1 : b = {R1, R3}
                    mma_bf16(c[mi][2 * nj + 1], ah[mi], bh4[1], bh4[3]);
                    mma_bf16(c[mi][2 * nj + 1], ah[mi], bl4[1], bl4[3]);
                    mma_bf16(c[mi][2 * nj + 1], al[mi], bh4[1], bh4[3]);
                }
            }
        }
    }

    // Epilogue
#pragma unroll
    for (int mi = 0; mi < 2; mi++)
#pragma unroll
    for (int na = 0; na < 8; na++) {
        int row = m0 + wm * 32 + mi * 16 + (lane >> 2);
        int col = n0 + wn * 64 + na * 8 + (lane & 3) * 2;
        float b0v = bias[col], b1v = bias[col + 1];
        float v0 = c[mi][na][0] + b0v, v1 = c[mi][na][1] + b1v;
        float v2 = c[mi][na][2] + b0v, v3 = c[mi][na][3] + b1v;
        size_t o0 = (size_t)row * EMB + col;
        size_t o1 = (size_t)(row + 8) * EMB + col;
        if (Cf) {
            *(float2*)&Cf[o0] = make_float2(v0, v1);
            *(float2*)&Cf[o1] = make_float2(v2, v3);
        } else {
            float h0 = bf16r(v0), h1 = bf16r(v1), h2 = bf16r(v2), h3 = bf16r(v3);
            *(uint32_t*)&Chi[o0] = pack2(v0, v1);
            *(uint32_t*)&Clo[o0] = pack2(v0 - h0, v1 - h1);
            *(uint32_t*)&Chi[o1] = pack2(v2, v3);
            *(uint32_t*)&Clo[o1] = pack2(v2 - h2, v3 - h3);
        }
    }
}

// ---------------------------------------------------------------------------
// Flash attention on mma.sync. Block = 128 q-rows x 1 head. 8 warps,
// warp owns 16 complete q-rows (softmax reductions stay in a lane quad).
// Q/K split bf16 (3 combos); P split in-register; V split via ldmatrix.trans.
// Writes split-bf16 attention output directly.
// ---------------------------------------------------------------------------
__global__ __launch_bounds__(256)
void flash_tc(const __nv_bfloat16* __restrict__ Qhi, const __nv_bfloat16* __restrict__ Qlo,
              const __nv_bfloat16* __restrict__ Khi, const __nv_bfloat16* __restrict__ Klo,
              const __nv_bfloat16* __restrict__ Vhi, const __nv_bfloat16* __restrict__ Vlo,
              __nv_bfloat16* __restrict__ Ohi, __nv_bfloat16* __restrict__ Olo)
{
    extern __shared__ __nv_bfloat16 sm[];
    __nv_bfloat16* sQh = sm;
    __nv_bfloat16* sQl = sQh + 128 * PADW;
    __nv_bfloat16* sKh = sQl + 128 * PADW;
    __nv_bfloat16* sKl = sKh + 64 * PADW;
    __nv_bfloat16* sVh = sKl + 64 * PADW;
    __nv_bfloat16* sVl = sVh + 64 * PADW;
    const uint32_t base = smem_u32(sm);
    const uint32_t bQh = base;
    const uint32_t bQl = bQh + 128 * PADW * 2;
    const uint32_t bKh = bQl + 128 * PADW * 2;
    const uint32_t bKl = bKh + 64 * PADW * 2;
    const uint32_t bVh = bKl + 64 * PADW * 2;
    const uint32_t bVl = bVh + 64 * PADW * 2;

    const int tid = threadIdx.x;
    const int lane = tid & 31;
    const int wid = tid >> 5;
    const int q0 = blockIdx.x * 128;
    const int hc = blockIdx.y * 64;

    // Load Q tiles once
#pragma unroll
    for (int it = 0; it < 4; it++) {
        int u = tid + it * 256;
        int r = u >> 3;
        int c8 = (u & 7) * 8;
        size_t g = (size_t)(q0 + r) * EMB + hc + c8;
        *(uint4*)(sQh + r * PADW + c8) = *(const uint4*)(Qhi + g);
        *(uint4*)(sQl + r * PADW + c8) = *(const uint4*)(Qlo + g);
    }

    float o[8][4];
    float mI[2], lI[2];
#pragma unroll
    for (int na = 0; na < 8; na++)
#pragma unroll
        for (int j = 0; j < 4; j++) o[na][j] = 0.0f;
    mI[0] = mI[1] = -1e30f;
    lI[0] = lI[1] = 0.0f;

    for (int t0 = 0; t0 < S_LEN; t0 += 64) {
        __syncthreads();   // previous iter's smem reads done (covers Q load too)
#pragma unroll
        for (int it = 0; it < 2; it++) {
            int u = tid + it * 256;      // 0..511
            int r = u >> 3;              // 0..63
            int c8 = (u & 7) * 8;
            size_t g = (size_t)(t0 + r) * EMB + hc + c8;
            *(uint4*)(sKh + r * PADW + c8) = *(const uint4*)(Khi + g);
            *(uint4*)(sKl + r * PADW + c8) = *(const uint4*)(Klo + g);
            *(uint4*)(sVh + r * PADW + c8) = *(const uint4*)(Vhi + g);
            *(uint4*)(sVl + r * PADW + c8) = *(const uint4*)(Vlo + g);
        }
        __syncthreads();

        // ---- S = Q K^T (16 q-rows x 64 t per warp) ----
        float s[8][4];
#pragma unroll
        for (int na = 0; na < 8; na++)
#pragma unroll
            for (int j = 0; j < 4; j++) s[na][j] = 0.0f;

#pragma unroll
        for (int kc = 0; kc < 4; kc++) {
            uint32_t qh[4], ql[4];
            uint32_t aoff = (uint32_t)(((wid * 16 + (lane & 15)) * PADW
                                        + kc * 16 + ((lane >> 4) << 3)) * 2);
            ldsm_x4(qh, bQh + aoff);
            ldsm_x4(ql, bQl + aoff);
#pragma unroll
            for (int nj = 0; nj < 4; nj++) {
                uint32_t kh4[4], kl4[4];
                uint32_t boff = (uint32_t)(((nj * 16 + (lane & 15)) * PADW
                                            + kc * 16 + ((lane >> 4) << 3)) * 2);
                ldsm_x4(kh4, bKh + boff);
                ldsm_x4(kl4, bKl + boff);
                mma_bf16(s[2 * nj], qh, kh4[0], kh4[2]);
                mma_bf16(s[2 * nj], qh, kl4[0], kl4[2]);
                mma_bf16(s[2 * nj], ql, kh4[0], kh4[2]);
                mma_bf16(s[2 * nj + 1], qh, kh4[1], kh4[3]);
                mma_bf16(s[2 * nj + 1], qh, kl4[1], kl4[3]);
                mma_bf16(s[2 * nj + 1], ql, kh4[1], kh4[3]);
            }
        }

        // ---- online softmax (rows: c{0,1}=row lane/4, c{2,3}=row+8) ----
#pragma unroll
        for (int ri = 0; ri < 2; ri++) {
            float rm = -1e30f;
#pragma unroll
            for (int na = 0; na < 8; na++) {
                s[na][2 * ri]     *= 0.125f;
                s[na][2 * ri + 1] *= 0.125f;
                rm = fmaxf(rm, fmaxf(s[na][2 * ri], s[na][2 * ri + 1]));
            }
            rm = fmaxf(rm, __shfl_xor_sync(0xffffffffu, rm, 1));
            rm = fmaxf(rm, __shfl_xor_sync(0xffffffffu, rm, 2));
            float mnew  = fmaxf(mI[ri], rm);
            float alpha = __expf(mI[ri] - mnew);
            float sum = 0.0f;
#pragma unroll
            for (int na = 0; na < 8; na++) {
                float p0 = __expf(s[na][2 * ri]     - mnew);
                float p1 = __expf(s[na][2 * ri + 1] - mnew);
                s[na][2 * ri] = p0;
                s[na][2 * ri + 1] = p1;
                sum += p0 + p1;
            }
            sum += __shfl_xor_sync(0xffffffffu, sum, 1);
            sum += __shfl_xor_sync(0xffffffffu, sum, 2);
            lI[ri] = lI[ri] * alpha + sum;
            mI[ri] = mnew;
#pragma unroll
            for (int na = 0; na < 8; na++) {
                o[na][2 * ri]     *= alpha;
                o[na][2 * ri + 1] *= alpha;
            }
        }

        // ---- O += P V  (P repacked in-register as A-fragments) ----
#pragma unroll
        for (int kc = 0; kc < 4; kc++) {
            float x0 = s[2 * kc][0], x1 = s[2 * kc][1];
            float x2 = s[2 * kc][2], x3 = s[2 * kc][3];
            float y0 = s[2 * kc + 1][0], y1 = s[2 * kc + 1][1];
            float y2 = s[2 * kc + 1][2], y3 = s[2 * kc + 1][3];
            uint32_t ph[4], pl[4];
            ph[0] = pack2(x0, x1);
            ph[1] = pack2(x2, x3);
            ph[2] = pack2(y0, y1);
            ph[3] = pack2(y2, y3);
            pl[0] = pack2(x0 - bf16r(x0), x1 - bf16r(x1));
            pl[1] = pack2(x2 - bf16r(x2), x3 - bf16r(x3));
            pl[2] = pack2(y0 - bf16r(y0), y1 - bf16r(y1));
            pl[3] = pack2(y2 - bf16r(y2), y3 - bf16r(y3));

#pragma unroll
            for (int nj = 0; nj < 4; nj++) {
                uint32_t vh4[4], vl4[4];
                uint32_t voff = (uint32_t)(((kc * 16 + ((lane >> 3) & 1) * 8 + (lane & 7)) * PADW
                                            + nj * 16 + (lane >> 4) * 8) * 2);
                ldsm_x4_t(vh4, bVh + voff);
                ldsm_x4_t(vl4, bVl + voff);
                // trans ordering: atom 2nj b={R0,R1}, atom 2nj+1 b={R2,R3}
                mma_bf16(o[2 * nj], ph, vh4[0], vh4[1]);
                mma_bf16(o[2 * nj], ph, vl4[0], vl4[1]);
                mma_bf16(o[2 * nj], pl, vh4[0], vh4[1]);
                mma_bf16(o[2 * nj + 1], ph, vh4[2], vh4[3]);
                mma_bf16(o[2 * nj + 1], ph, vl4[2], vl4[3]);
                mma_bf16(o[2 * nj + 1], pl, vh4[2], vh4[3]);
            }
        }
    }

    // ---- epilogue: normalize, split to bf16 hi/lo, store ----
#pragma unroll
    for (int ri = 0; ri < 2; ri++) {
        float inv = 1.0f / lI[ri];
        int row = q0 + wid * 16 + (lane >> 2) + ri * 8;
#pragma unroll
        for (int na = 0; na < 8; na++) {
            int col = hc + na * 8 + (lane & 3) * 2;
            float v0 = o[na][2 * ri] * inv;
            float v1 = o[na][2 * ri + 1] * inv;
            float h0 = bf16r(v0), h1 = bf16r(v1);
            size_t off = (size_t)row * EMB + col;
            *(uint32_t*)&Ohi[off] = pack2(v0, v1);
            *(uint32_t*)&Olo[off] = pack2(v0 - h0, v1 - h1);
        }
    }
}

// ---------------------------------------------------------------------------
// Launch
// ---------------------------------------------------------------------------
extern "C" void kernel_launch(void* const* d_in, const int* in_sizes, int n_in,
                              void* d_out, int out_size)
{
    const float* x  = (const float*)d_in[0];
    const float* Wq = (const float*)d_in[1];
    const float* bq = (const float*)d_in[2];
    const float* Wk = (const float*)d_in[3];
    const float* bk = (const float*)d_in[4];
    const float* Wv = (const float*)d_in[5];
    const float* bv = (const float*)d_in[6];
    const float* Wo = (const float*)d_in[7];
    const float* bo = (const float*)d_in[8];
    float* out = (float*)d_out;

    __nv_bfloat16 *xhi, *xlo, *whi, *wlo, *qhi, *qlo, *khi, *klo, *vhi, *vlo, *ahi, *alo;
    cudaGetSymbolAddress((void**)&xhi, g_xhi);
    cudaGetSymbolAddress((void**)&xlo, g_xlo);
    cudaGetSymbolAddress((void**)&whi, g_whi);
    cudaGetSymbolAddress((void**)&wlo, g_wlo);
    cudaGetSymbolAddress((void**)&qhi, g_qhi);
    cudaGetSymbolAddress((void**)&qlo, g_qlo);
    cudaGetSymbolAddress((void**)&khi, g_khi);
    cudaGetSymbolAddress((void**)&klo, g_klo);
    cudaGetSymbolAddress((void**)&vhi, g_vhi);
    cudaGetSymbolAddress((void**)&vlo, g_vlo);
    cudaGetSymbolAddress((void**)&ahi, g_ahi);
    cudaGetSymbolAddress((void**)&alo, g_alo);

    const int GSM = 4 * 128 * PADW * 2;                 // 73728 B
    const int FSM = (2 * 128 + 4 * 64) * PADW * 2;      // 73728 B
    cudaFuncSetAttribute(gemm_tc,  cudaFuncAttributeMaxDynamicSharedMemorySize, GSM);
    cudaFuncSetAttribute(flash_tc, cudaFuncAttributeMaxDynamicSharedMemorySize, FSM);

    const int NW = EMB * EMB;
    const int n4x = S_LEN * EMB / 4;   // 1Mi float4
    const int n4w = NW / 4;            // 256Ki float4

    split4_kernel<<<(n4x + 255) / 256, 256>>>((const float4*)x, (uint2*)xhi, (uint2*)xlo, n4x);
    split4_kernel<<<(n4w + 255) / 256, 256>>>((const float4*)Wq, (uint2*)(whi + 0 * NW), (uint2*)(wlo + 0 * NW), n4w);
    split4_kernel<<<(n4w + 255) / 256, 256>>>((const float4*)Wk, (uint2*)(whi + 1 * NW), (uint2*)(wlo + 1 * NW), n4w);
    split4_kernel<<<(n4w + 255) / 256, 256>>>((const float4*)Wv, (uint2*)(whi + 2 * NW), (uint2*)(wlo + 2 * NW), n4w);
    split4_kernel<<<(n4w + 255) / 256, 256>>>((const float4*)Wo, (uint2*)(whi + 3 * NW), (uint2*)(wlo + 3 * NW), n4w);

    dim3 gg(EMB / 128, S_LEN / 128);   // (8, 32)
    gemm_tc<<<gg, 256, GSM>>>(xhi, xlo, whi + 0 * NW, wlo + 0 * NW, bq, nullptr, qhi, qlo);
    gemm_tc<<<gg, 256, GSM>>>(xhi, xlo, whi + 1 * NW, wlo + 1 * NW, bk, nullptr, khi, klo);
    gemm_tc<<<gg, 256, GSM>>>(xhi, xlo, whi + 2 * NW, wlo + 2 * NW, bv, nullptr, vhi, vlo);

    dim3 fg(S_LEN / 128, 16);          // (32, 16)
    flash_tc<<<fg, 256, FSM>>>(qhi, qlo, khi, klo, vhi, vlo, ahi, alo);

    gemm_tc<<<gg, 256, GSM>>>(ahi, alo, whi + 3 * NW, wlo + 3 * NW, bo, out, nullptr, nullptr);
}